// round 14
// baseline (speedup 1.0000x reference)
#include <cuda_runtime.h>
#include <cuda_fp16.h>
#include <math.h>
#include <stdint.h>

// Problem constants (b=2, c=64, H=480, W=640, gs=8 -> hc=60, wc=80, n=4800)
#define BQ 2
#define CC 64
#define HC 60
#define WCC 80
#define NN 4800
#define HH 480
#define WW 640
#define EPSF 1e-8f
#define NEGBIG -1e30f
#define VISBIAS -30000.0f

// GEMM: M=N=4800 (pad 4864), K=128 fp16 (64 hi | 63 lo | bias), 128x128 tiles
// Each block: 1 mtile x 2 ntiles (A reused, B double-streamed)
#define KH 128
#define NPAD 4864
#define MT 38
#define NTG 19                         // ntile pairs
#define TOTALB (NTG * MT * BQ)         // 1444
#define ROWB 272                       // 17 x 16B, odd -> conflict-free
#define CHUNK (128 * ROWB)             // 34816 bytes per matrix tile
#define SMEM_BYTES (3 * CHUNK)         // A + B0 + B1 = 104448

// ---------------- scratch (no allocations allowed) ----------------
__device__ float    g_visNeg[BQ * NN];     // 0 if visible else -1e30
__device__ float    g_posSim[BQ * NN];
__device__ float    g_match[BQ * NN];
__device__ int      g_neigh[BQ * NN * 4];
__device__ int      g_negMinI[BQ * NN];
__device__ unsigned g_ctr;
__device__ __align__(16) __half g_Ah[(size_t)BQ * NPAD * KH];
__device__ __align__(16) __half g_Bh[(size_t)BQ * NPAD * KH];

__device__ __forceinline__ uint32_t smem_u32(const void* p) {
    uint32_t a;
    asm("{ .reg .u64 t; cvta.to.shared.u64 t, %1; cvt.u32.u64 %0, t; }"
        : "=r"(a) : "l"(p));
    return a;
}
__device__ __forceinline__ void ldsm4(uint32_t* r, uint32_t addr) {
    asm volatile("ldmatrix.sync.aligned.m8n8.x4.shared.b16 {%0,%1,%2,%3}, [%4];"
                 : "=r"(r[0]), "=r"(r[1]), "=r"(r[2]), "=r"(r[3]) : "r"(addr));
}
__device__ __forceinline__ void mma16816(float* c, const uint32_t* a,
                                         uint32_t b0, uint32_t b1) {
    asm volatile(
        "mma.sync.aligned.m16n8k16.row.col.f32.f16.f16.f32 "
        "{%0,%1,%2,%3}, {%4,%5,%6,%7}, {%8,%9}, {%0,%1,%2,%3};"
        : "+f"(c[0]), "+f"(c[1]), "+f"(c[2]), "+f"(c[3])
        : "r"(a[0]), "r"(a[1]), "r"(a[2]), "r"(a[3]), "r"(b0), "r"(b1));
}
__device__ __forceinline__ void cp16(uint32_t dst, const void* src) {
    asm volatile("cp.async.cg.shared.global [%0], [%1], 16;"
                 :: "r"(dst), "l"(src) : "memory");
}
#define CP_COMMIT() asm volatile("cp.async.commit_group;" ::: "memory")
#define CP_WAIT(n)  asm volatile("cp.async.wait_group %0;" :: "n"(n) : "memory")

__device__ __forceinline__ float inb_grid(float yi, float xi) {
    return (yi >= 0.f && yi <= (float)(HC - 1) && xi >= 0.f && xi <= (float)(WCC - 1)) ? 1.f : 0.f;
}

// ====== Kernel 0: per-row prep, 8 THREADS per row (parallel + coalesced) ====
__global__ void prep_kernel(const float* __restrict__ desc1,
                            const float* __restrict__ desc2,
                            const float* __restrict__ homo12,
                            const float* __restrict__ homo21) {
    int t8 = blockIdx.x * 256 + threadIdx.x;
    if (t8 == 0) g_ctr = 0u;
    int t = t8 >> 3;          // global row id (b*NN + r)
    int p = t8 & 7;           // part 0..7
    if (t >= BQ * NN) return;
    int b = t / NN, r = t % NN;
    int iy = r / WCC, ix = r % WCC;

    // ---- visibility: one dy-row of 8 pixels per part, division-free ----
    {
        const float* h = homo21 + b * 9;
        float h0 = h[0], h1 = h[1], h2 = h[2], h3 = h[3], h4 = h[4],
              h5 = h[5], h6 = h[6], h7 = h[7], h8 = h[8];
        float cx0 = (float)(ix * 8);
        float y = (float)(iy * 8 + p);
        float qxr = h0 * cx0 + h1 * y + h2;
        float qyr = h3 * cx0 + h4 * y + h5;
        float qzr = h6 * cx0 + h7 * y + h8;
        bool ok = true;
#pragma unroll
        for (int dx = 0; dx < 8; ++dx) {
            float qx = qxr + h0 * (float)dx;
            float qy = qyr + h3 * (float)dx;
            float z  = qzr + h6 * (float)dx + EPSF;
            ok = ok && ((qy + z) * z > 0.f)
                    && (((float)HH * z - qy) * z > 0.f)
                    && ((qx + z) * z > 0.f)
                    && (((float)WW * z - qx) * z > 0.f);
        }
        unsigned oku = ok ? 1u : 0u;
        oku &= __shfl_xor_sync(0xffffffffu, oku, 1);
        oku &= __shfl_xor_sync(0xffffffffu, oku, 2);
        oku &= __shfl_xor_sync(0xffffffffu, oku, 4);
        if (p == 0) {
            g_visNeg[t] = oku ? 0.f : NEGBIG;
            g_negMinI[t] = 0x7F800000;
        }
    }

    // ---- warp point under homo12 (all parts, cheap) ----
    const float* h = homo12 + b * 9;
    float px = (float)(ix * 8) + 3.5f;
    float py = (float)(iy * 8) + 3.5f;
    float qx = h[0] * px + h[1] * py + h[2];
    float qy = h[3] * px + h[4] * py + h[5];
    float qz = h[6] * px + h[7] * py + h[8];
    float wx = qx / (qz + EPSF);
    float wy = qy / (qz + EPSF);
    float dyc = (wy - 3.5f) * 0.125f;
    float dxc = (wx - 3.5f) * 0.125f;

    // ---- 4-NN in clamped 4x4 window (part 0 only; tie -> lower index) ----
    if (p == 0) {
        float a2 = wy * wy + wx * wx;
        int xlo = (int)fminf(fmaxf(floorf(dxc) - 1.f, 0.f), (float)(WCC - 4));
        int ylo = (int)fminf(fmaxf(floorf(dyc) - 1.f, 0.f), (float)(HC - 4));
        float bd[4] = {1e30f, 1e30f, 1e30f, 1e30f};
        int bi[4] = {-1, -1, -1, -1};
#pragma unroll
        for (int jy = 0; jy < 4; ++jy) {
            int iyc = ylo + jy;
            float cy = (float)(iyc * 8) + 3.5f;
#pragma unroll
            for (int jx = 0; jx < 4; ++jx) {
                int ixc = xlo + jx;
                float cx = (float)(ixc * 8) + 3.5f;
                float d = a2 + cy * cy + cx * cx - 2.f * (wy * cy + wx * cx);
                int m = iyc * WCC + ixc;
                if (d < bd[3]) {
                    int k = 3;
                    while (k > 0 && d < bd[k - 1]) {
                        bd[k] = bd[k - 1]; bi[k] = bi[k - 1]; --k;
                    }
                    bd[k] = d; bi[k] = m;
                }
            }
        }
        int* o = &g_neigh[(size_t)t * 4];
        o[0] = bi[0]; o[1] = bi[1]; o[2] = bi[2]; o[3] = bi[3];
    }

    // ---- bilinear w_desc1 + pos_sim: 8 channels per part ----
    float y0 = floorf(dyc), x0 = floorf(dxc);
    float fy = dyc - y0, fx = dxc - x0;
    float e00 = (1.f - fy) * (1.f - fx) * inb_grid(y0, x0);
    float e01 = (1.f - fy) * fx         * inb_grid(y0, x0 + 1.f);
    float e10 = fy * (1.f - fx)         * inb_grid(y0 + 1.f, x0);
    float e11 = fy * fx                 * inb_grid(y0 + 1.f, x0 + 1.f);
    int yc0 = (int)fminf(fmaxf(y0, 0.f), (float)(HC - 1));
    int yc1 = (int)fminf(fmaxf(y0 + 1.f, 0.f), (float)(HC - 1));
    int xc0 = (int)fminf(fmaxf(x0, 0.f), (float)(WCC - 1));
    int xc1 = (int)fminf(fmaxf(x0 + 1.f, 0.f), (float)(WCC - 1));
    int c00 = yc0 * WCC + xc0, c01 = yc0 * WCC + xc1;
    int c10 = yc1 * WCC + xc0, c11 = yc1 * WCC + xc1;

    const float* d2b = desc2 + ((size_t)b * CC + p * 8) * NN;
    const float* d1b = desc1 + ((size_t)b * CC + p * 8) * NN + r;
    float sq = 0.f, dp = 0.f;
#pragma unroll
    for (int i = 0; i < 8; ++i) {
        const float* pp = d2b + (size_t)i * NN;
        float v = e00 * pp[c00] + e01 * pp[c01] + e10 * pp[c10] + e11 * pp[c11];
        sq += v * v;
        dp += d1b[(size_t)i * NN] * v;
    }
    sq += __shfl_xor_sync(0xffffffffu, sq, 1);
    dp += __shfl_xor_sync(0xffffffffu, dp, 1);
    sq += __shfl_xor_sync(0xffffffffu, sq, 2);
    dp += __shfl_xor_sync(0xffffffffu, dp, 2);
    sq += __shfl_xor_sync(0xffffffffu, sq, 4);
    dp += __shfl_xor_sync(0xffffffffu, dp, 4);

    if (p == 0) {
        float posdot = dp / (sqrtf(sq) + EPSF);
        g_posSim[t] = sqrtf(fmaxf(2.f - 2.f * posdot, EPSF));
        g_match[t] =
            (wy >= 0.f && wy <= (float)(HH - 1) && wx >= 0.f && wx <= (float)(WW - 1)) ? 1.f : 0.f;
    }
}

// ====== Kernel 1: f32 -> fp16 split scratch (64 hi | 63 lo | bias chan) =====
__global__ void split_kernel(const float* __restrict__ desc1,
                             const float* __restrict__ desc2) {
    __shared__ float sd[CC][129];
    int b = blockIdx.y;
    int row0 = blockIdx.x * 128;
    int tid = threadIdx.x;   // 256 threads

    for (int i = tid; i < CC * 128; i += 256) {
        int ch = i >> 7, r = i & 127;
        int gr = row0 + r;
        sd[ch][r] = (gr < NN) ? desc1[(size_t)(b * CC + ch) * NN + gr] : 0.f;
    }
    __syncthreads();
    for (int i = tid; i < 128 * KH; i += 256) {
        int r = i >> 7, k = i & 127;
        __half o;
        if (k < 64) {
            o = __float2half_rn(sd[k][r]);
        } else if (k < 127) {
            float v = sd[k - 64][r];
            __half hi = __float2half_rn(v);
            o = __float2half_rn(v - __half2float(hi));
        } else {
            o = __float2half_rn(1.0f);        // bias channel
        }
        g_Ah[((size_t)b * NPAD + row0 + r) * KH + k] = o;
    }
    __syncthreads();

    for (int i = tid; i < CC * 128; i += 256) {
        int ch = i >> 7, r = i & 127;
        int gr = row0 + r;
        sd[ch][r] = (gr < NN) ? desc2[(size_t)(b * CC + ch) * NN + gr] : 0.f;
    }
    __syncthreads();
    for (int i = tid; i < 128 * KH; i += 256) {
        int r = i >> 7, k = i & 127;
        int gr = row0 + r;
        __half o;
        if (k < 64) {
            o = __float2half_rn(sd[k][r]);
        } else if (k < 127) {
            float v = sd[k - 64][r];
            __half hi = __float2half_rn(v);
            o = __float2half_rn(v - __half2float(hi));
        } else {
            // vis bias: 0 if visible in-range column, else -30000
            float vb = (gr < NN && g_visNeg[b * NN + gr] == 0.f) ? 0.f : VISBIAS;
            o = __float2half_rn(vb);
        }
        g_Bh[((size_t)b * NPAD + row0 + r) * KH + k] = o;
    }
}

// ====== Kernel 2: fp16 GEMM, 1 mtile x 2 ntiles, A reused, B pipelined ======
// Round-12 structure (per-ntile epilogue + commit); vis baked into K.
__global__ void __launch_bounds__(128, 2)
mma_kernel(float* __restrict__ out) {
    extern __shared__ char sm[];
    __shared__ int4  s_nb[128];        // absolute neighbor cols for my 128 rows
    __shared__ float s_red[2][128];
    __shared__ int   s_last;
    __shared__ float rL[4], rM[4];

    int tid = threadIdx.x;
    int wid = tid >> 5, l = tid & 31;
    int wm = wid & 1, wn = wid >> 1;        // 2 x 2 warp grid
    int ntg = blockIdx.x, mtile = blockIdx.y, b = blockIdx.z;

    uint32_t au = smem_u32(sm);
    const __half* Asrc = g_Ah + ((size_t)b * NPAD + mtile * 128) * KH;

    // group 0: A tile (reused for both ntiles)
#pragma unroll
    for (int tq = 0; tq < 16; ++tq) {
        int i = tq * 128 + tid, rr = i >> 4, g = i & 15;
        cp16(au + rr * ROWB + g * 16, Asrc + (size_t)rr * KH + g * 8);
    }
    CP_COMMIT();
    // groups 1,2: B tiles for ntile = ntg*2 + n
#pragma unroll
    for (int n = 0; n < 2; ++n) {
        const __half* Bsrc = g_Bh + ((size_t)b * NPAD + (ntg * 2 + n) * 128) * KH;
        uint32_t bb = au + (1 + n) * CHUNK;
#pragma unroll
        for (int tq = 0; tq < 16; ++tq) {
            int i = tq * 128 + tid, rr = i >> 4, g = i & 15;
            cp16(bb + rr * ROWB + g * 16, Bsrc + (size_t)rr * KH + g * 8);
        }
        CP_COMMIT();
    }

    // stage neighbor indices while loads fly
    {
        int grow = mtile * 128 + tid;
        int gr = grow < NN ? grow : NN - 1;
        s_nb[tid] = *reinterpret_cast<const int4*>(&g_neigh[((size_t)b * NN + gr) * 4]);
    }

    // ldmatrix per-lane row offsets (warp tile 64x64)
    int lane7 = l & 7, mat = l >> 3, kh = mat >> 1;
    uint32_t arow[4], brow[4];
#pragma unroll
    for (int mf = 0; mf < 4; ++mf)
        arow[mf] = (uint32_t)(wm * 64 + mf * 16 + (mat & 1) * 8 + lane7) * ROWB;
#pragma unroll
    for (int bf = 0; bf < 4; ++bf)
        brow[bf] = (uint32_t)(wn * 64 + bf * 16 + (mat & 1) * 8 + lane7) * ROWB;

    // process the two ntiles sequentially (per-ntile epilogue + commit)
#pragma unroll
    for (int n = 0; n < 2; ++n) {
        if (n == 0) CP_WAIT(1);   // A + B0 landed (B1 still streaming)
        else        CP_WAIT(0);   // B1 landed
        __syncthreads();

        float cfr[4][8][4];
#pragma unroll
        for (int mf = 0; mf < 4; ++mf)
#pragma unroll
            for (int nf = 0; nf < 8; ++nf)
#pragma unroll
                for (int q = 0; q < 4; ++q) cfr[mf][nf][q] = 0.f;

        uint32_t bbase = au + (1 + n) * CHUNK;
#pragma unroll
        for (int ks = 0; ks < 8; ++ks) {
            uint32_t g16 = (uint32_t)((ks * 2 + kh) << 4);
            uint32_t af[4][4], bq[4][4];
#pragma unroll
            for (int mf = 0; mf < 4; ++mf) ldsm4(af[mf], au + arow[mf] + g16);
#pragma unroll
            for (int bf = 0; bf < 4; ++bf) ldsm4(bq[bf], bbase + brow[bf] + g16);
#pragma unroll
            for (int mf = 0; mf < 4; ++mf)
#pragma unroll
                for (int nf = 0; nf < 8; ++nf)
                    mma16816(cfr[mf][nf], af[mf],
                             bq[nf >> 1][nf & 1], bq[nf >> 1][2 + (nf & 1)]);
        }

        // epilogue for this ntile: neighbor-masked max per row (vis in K)
        int colbase = (ntg * 2 + n) * 128;
#pragma unroll
        for (int mf = 0; mf < 4; ++mf) {
#pragma unroll
            for (int half = 0; half < 2; ++half) {
                int rl = wm * 64 + mf * 16 + (l >> 2) + half * 8;
                int4 nb = s_nb[rl];
                float mx = NEGBIG;
#pragma unroll
                for (int nf = 0; nf < 8; ++nf) {
                    int gc0 = colbase + wn * 64 + nf * 8 + (l & 3) * 2;
                    int gc1 = gc0 + 1;
                    float v0 = cfr[mf][nf][half * 2 + 0];
                    float v1 = cfr[mf][nf][half * 2 + 1];
                    bool m0 = (nb.x == gc0) | (nb.y == gc0) | (nb.z == gc0) | (nb.w == gc0);
                    bool m1 = (nb.x == gc1) | (nb.y == gc1) | (nb.z == gc1) | (nb.w == gc1);
                    mx = fmaxf(mx, m0 ? NEGBIG : v0);
                    mx = fmaxf(mx, m1 ? NEGBIG : v1);
                }
                mx = fmaxf(mx, __shfl_xor_sync(0xffffffffu, mx, 1));
                mx = fmaxf(mx, __shfl_xor_sync(0xffffffffu, mx, 2));
                if ((l & 3) == 0) s_red[wn][rl] = mx;
            }
        }
        __syncthreads();
        {
            float m = fmaxf(s_red[0][tid], s_red[1][tid]);
            int grow = mtile * 128 + tid;
            if (grow < NN) {
                float neg = sqrtf(fmaxf(2.f - 2.f * m, EPSF));
                atomicMin(&g_negMinI[b * NN + grow], __float_as_int(neg));
            }
        }
        __syncthreads();
    }

    // last block: deterministic final reduction
    if (tid == 0) {
        __threadfence();
        s_last = (atomicAdd(&g_ctr, 1u) == TOTALB - 1) ? 1 : 0;
    }
    __syncthreads();
    if (s_last) {
        __threadfence();
        float aL = 0.f, aM = 0.f;
        for (int i = tid; i < BQ * NN; i += 128) {
            float neg = __int_as_float(g_negMinI[i]);
            float lv = fmaxf(g_posSim[i] - neg + 1.0f, 0.f);
            float mm = g_match[i];
            aL += lv * lv * mm;
            aM += mm;
        }
#pragma unroll
        for (int off = 16; off; off >>= 1) {
            aL += __shfl_xor_sync(0xffffffffu, aL, off);
            aM += __shfl_xor_sync(0xffffffffu, aM, off);
        }
        if (l == 0) { rL[wid] = aL; rM[wid] = aM; }
        __syncthreads();
        if (tid == 0) {
            float sL = 0.f, sM = 0.f;
#pragma unroll
            for (int q = 0; q < 4; ++q) { sL += rL[q]; sM += rM[q]; }
            out[0] = sL / sM;
        }
    }
}

// ---------------- launch ----------------
extern "C" void kernel_launch(void* const* d_in, const int* in_sizes, int n_in,
                              void* d_out, int out_size) {
    // metadata order: score1, score2, desc1, desc2, homo12, homo21
    const float* desc1  = (const float*)d_in[2];
    const float* desc2  = (const float*)d_in[3];
    const float* homo12 = (const float*)d_in[4];
    const float* homo21 = (const float*)d_in[5];

    cudaFuncSetAttribute(mma_kernel, cudaFuncAttributeMaxDynamicSharedMemorySize,
                         SMEM_BYTES);
    prep_kernel<<<(BQ * NN * 8 + 255) / 256, 256>>>(desc1, desc2, homo12, homo21);
    split_kernel<<<dim3(MT, BQ), 256>>>(desc1, desc2);
    dim3 g(NTG, MT, BQ);
    mma_kernel<<<g, 128, SMEM_BYTES>>>((float*)d_out);
}

// round 15
// speedup vs baseline: 1.1333x; 1.1333x over previous
#include <cuda_runtime.h>
#include <cuda_fp16.h>
#include <math.h>
#include <stdint.h>

// Problem constants (b=2, c=64, H=480, W=640, gs=8 -> hc=60, wc=80, n=4800)
#define BQ 2
#define CC 64
#define HC 60
#define WCC 80
#define NN 4800
#define HH 480
#define WW 640
#define EPSF 1e-8f
#define NEGBIG -1e30f

// GEMM: M=N=4800 (pad 4864), K=128 fp16 (hi|lo split), 128x128 tiles
// Each block: 1 mtile x 2 ntiles (A reused, B double-streamed)
#define KH 128
#define NPAD 4864
#define MT 38
#define NTG 19                         // ntile pairs
#define TOTALB (NTG * MT * BQ)         // 1444
#define ROWB 272                       // 17 x 16B, odd -> conflict-free
#define CHUNK (128 * ROWB)             // 34816 bytes per matrix tile
#define SMEM_BYTES (3 * CHUNK)         // A + B0 + B1 = 104448

// ---------------- scratch (no allocations allowed) ----------------
__device__ float    g_visNeg[BQ * NN];     // 0 if visible else -1e30
__device__ float    g_posSim[BQ * NN];
__device__ float    g_match[BQ * NN];
__device__ int      g_neigh[BQ * NN * 4];
__device__ int      g_negMinI[BQ * NN];
__device__ unsigned g_ctr;
__device__ __align__(16) __half g_Ah[(size_t)BQ * NPAD * KH];
__device__ __align__(16) __half g_Bh[(size_t)BQ * NPAD * KH];

__device__ __forceinline__ uint32_t smem_u32(const void* p) {
    uint32_t a;
    asm("{ .reg .u64 t; cvta.to.shared.u64 t, %1; cvt.u32.u64 %0, t; }"
        : "=r"(a) : "l"(p));
    return a;
}
__device__ __forceinline__ void ldsm4(uint32_t* r, uint32_t addr) {
    asm volatile("ldmatrix.sync.aligned.m8n8.x4.shared.b16 {%0,%1,%2,%3}, [%4];"
                 : "=r"(r[0]), "=r"(r[1]), "=r"(r[2]), "=r"(r[3]) : "r"(addr));
}
__device__ __forceinline__ void mma16816(float* c, const uint32_t* a,
                                         uint32_t b0, uint32_t b1) {
    asm volatile(
        "mma.sync.aligned.m16n8k16.row.col.f32.f16.f16.f32 "
        "{%0,%1,%2,%3}, {%4,%5,%6,%7}, {%8,%9}, {%0,%1,%2,%3};"
        : "+f"(c[0]), "+f"(c[1]), "+f"(c[2]), "+f"(c[3])
        : "r"(a[0]), "r"(a[1]), "r"(a[2]), "r"(a[3]), "r"(b0), "r"(b1));
}
__device__ __forceinline__ void cp16(uint32_t dst, const void* src) {
    asm volatile("cp.async.cg.shared.global [%0], [%1], 16;"
                 :: "r"(dst), "l"(src) : "memory");
}
#define CP_COMMIT() asm volatile("cp.async.commit_group;" ::: "memory")
#define CP_WAIT(n)  asm volatile("cp.async.wait_group %0;" :: "n"(n) : "memory")

__device__ __forceinline__ float inb_grid(float yi, float xi) {
    return (yi >= 0.f && yi <= (float)(HC - 1) && xi >= 0.f && xi <= (float)(WCC - 1)) ? 1.f : 0.f;
}

// ====== Kernel 0: per-row prep, 8 THREADS per row (parallel + coalesced) ====
__global__ void prep_kernel(const float* __restrict__ desc1,
                            const float* __restrict__ desc2,
                            const float* __restrict__ homo12,
                            const float* __restrict__ homo21) {
    int t8 = blockIdx.x * 256 + threadIdx.x;
    if (t8 == 0) g_ctr = 0u;
    int t = t8 >> 3;          // global row id (b*NN + r)
    int p = t8 & 7;           // part 0..7
    if (t >= BQ * NN) return;
    int b = t / NN, r = t % NN;
    int iy = r / WCC, ix = r % WCC;

    // ---- visibility: one dy-row of 8 pixels per part, division-free ----
    {
        const float* h = homo21 + b * 9;
        float h0 = h[0], h1 = h[1], h2 = h[2], h3 = h[3], h4 = h[4],
              h5 = h[5], h6 = h[6], h7 = h[7], h8 = h[8];
        float cx0 = (float)(ix * 8);
        float y = (float)(iy * 8 + p);
        float qxr = h0 * cx0 + h1 * y + h2;
        float qyr = h3 * cx0 + h4 * y + h5;
        float qzr = h6 * cx0 + h7 * y + h8;
        bool ok = true;
#pragma unroll
        for (int dx = 0; dx < 8; ++dx) {
            float qx = qxr + h0 * (float)dx;
            float qy = qyr + h3 * (float)dx;
            float z  = qzr + h6 * (float)dx + EPSF;
            ok = ok && ((qy + z) * z > 0.f)
                    && (((float)HH * z - qy) * z > 0.f)
                    && ((qx + z) * z > 0.f)
                    && (((float)WW * z - qx) * z > 0.f);
        }
        unsigned oku = ok ? 1u : 0u;
        oku &= __shfl_xor_sync(0xffffffffu, oku, 1);
        oku &= __shfl_xor_sync(0xffffffffu, oku, 2);
        oku &= __shfl_xor_sync(0xffffffffu, oku, 4);
        if (p == 0) {
            g_visNeg[t] = oku ? 0.f : NEGBIG;
            g_negMinI[t] = 0x7F800000;
        }
    }

    // ---- warp point under homo12 (all parts, cheap) ----
    const float* h = homo12 + b * 9;
    float px = (float)(ix * 8) + 3.5f;
    float py = (float)(iy * 8) + 3.5f;
    float qx = h[0] * px + h[1] * py + h[2];
    float qy = h[3] * px + h[4] * py + h[5];
    float qz = h[6] * px + h[7] * py + h[8];
    float wx = qx / (qz + EPSF);
    float wy = qy / (qz + EPSF);
    float dyc = (wy - 3.5f) * 0.125f;
    float dxc = (wx - 3.5f) * 0.125f;

    // ---- 4-NN in clamped 4x4 window (part 0 only; tie -> lower index) ----
    if (p == 0) {
        float a2 = wy * wy + wx * wx;
        int xlo = (int)fminf(fmaxf(floorf(dxc) - 1.f, 0.f), (float)(WCC - 4));
        int ylo = (int)fminf(fmaxf(floorf(dyc) - 1.f, 0.f), (float)(HC - 4));
        float bd[4] = {1e30f, 1e30f, 1e30f, 1e30f};
        int bi[4] = {-1, -1, -1, -1};
#pragma unroll
        for (int jy = 0; jy < 4; ++jy) {
            int iyc = ylo + jy;
            float cy = (float)(iyc * 8) + 3.5f;
#pragma unroll
            for (int jx = 0; jx < 4; ++jx) {
                int ixc = xlo + jx;
                float cx = (float)(ixc * 8) + 3.5f;
                float d = a2 + cy * cy + cx * cx - 2.f * (wy * cy + wx * cx);
                int m = iyc * WCC + ixc;
                if (d < bd[3]) {
                    int k = 3;
                    while (k > 0 && d < bd[k - 1]) {
                        bd[k] = bd[k - 1]; bi[k] = bi[k - 1]; --k;
                    }
                    bd[k] = d; bi[k] = m;
                }
            }
        }
        int* o = &g_neigh[(size_t)t * 4];
        o[0] = bi[0]; o[1] = bi[1]; o[2] = bi[2]; o[3] = bi[3];
    }

    // ---- bilinear w_desc1 + pos_sim: 8 channels per part ----
    float y0 = floorf(dyc), x0 = floorf(dxc);
    float fy = dyc - y0, fx = dxc - x0;
    float e00 = (1.f - fy) * (1.f - fx) * inb_grid(y0, x0);
    float e01 = (1.f - fy) * fx         * inb_grid(y0, x0 + 1.f);
    float e10 = fy * (1.f - fx)         * inb_grid(y0 + 1.f, x0);
    float e11 = fy * fx                 * inb_grid(y0 + 1.f, x0 + 1.f);
    int yc0 = (int)fminf(fmaxf(y0, 0.f), (float)(HC - 1));
    int yc1 = (int)fminf(fmaxf(y0 + 1.f, 0.f), (float)(HC - 1));
    int xc0 = (int)fminf(fmaxf(x0, 0.f), (float)(WCC - 1));
    int xc1 = (int)fminf(fmaxf(x0 + 1.f, 0.f), (float)(WCC - 1));
    int c00 = yc0 * WCC + xc0, c01 = yc0 * WCC + xc1;
    int c10 = yc1 * WCC + xc0, c11 = yc1 * WCC + xc1;

    const float* d2b = desc2 + ((size_t)b * CC + p * 8) * NN;
    const float* d1b = desc1 + ((size_t)b * CC + p * 8) * NN + r;
    float sq = 0.f, dp = 0.f;
#pragma unroll
    for (int i = 0; i < 8; ++i) {
        const float* pp = d2b + (size_t)i * NN;
        float v = e00 * pp[c00] + e01 * pp[c01] + e10 * pp[c10] + e11 * pp[c11];
        sq += v * v;
        dp += d1b[(size_t)i * NN] * v;
    }
    sq += __shfl_xor_sync(0xffffffffu, sq, 1);
    dp += __shfl_xor_sync(0xffffffffu, dp, 1);
    sq += __shfl_xor_sync(0xffffffffu, sq, 2);
    dp += __shfl_xor_sync(0xffffffffu, dp, 2);
    sq += __shfl_xor_sync(0xffffffffu, sq, 4);
    dp += __shfl_xor_sync(0xffffffffu, dp, 4);

    if (p == 0) {
        float posdot = dp / (sqrtf(sq) + EPSF);
        g_posSim[t] = sqrtf(fmaxf(2.f - 2.f * posdot, EPSF));
        g_match[t] =
            (wy >= 0.f && wy <= (float)(HH - 1) && wx >= 0.f && wx <= (float)(WW - 1)) ? 1.f : 0.f;
    }
}

// ====== Kernel 1: f32 -> fp16 hi|lo split scratch (K = 64 hi + 64 lo) ======
__global__ void split_kernel(const float* __restrict__ desc1,
                             const float* __restrict__ desc2) {
    __shared__ float sd[CC][129];
    int b = blockIdx.y;
    int row0 = blockIdx.x * 128;
    int tid = threadIdx.x;   // 256 threads

    for (int i = tid; i < CC * 128; i += 256) {
        int ch = i >> 7, r = i & 127;
        int gr = row0 + r;
        sd[ch][r] = (gr < NN) ? desc1[(size_t)(b * CC + ch) * NN + gr] : 0.f;
    }
    __syncthreads();
    for (int i = tid; i < 128 * KH; i += 256) {
        int r = i >> 7, k = i & 127;
        float v = sd[k & 63][r];
        __half hi = __float2half_rn(v);
        __half o = (k < 64) ? hi : __float2half_rn(v - __half2float(hi));
        g_Ah[((size_t)b * NPAD + row0 + r) * KH + k] = o;
    }
    __syncthreads();

    for (int i = tid; i < CC * 128; i += 256) {
        int ch = i >> 7, r = i & 127;
        int gr = row0 + r;
        sd[ch][r] = (gr < NN) ? desc2[(size_t)(b * CC + ch) * NN + gr] : 0.f;
    }
    __syncthreads();
    for (int i = tid; i < 128 * KH; i += 256) {
        int r = i >> 7, k = i & 127;
        float v = sd[k & 63][r];
        __half hi = __float2half_rn(v);
        __half o = (k < 64) ? hi : __float2half_rn(v - __half2float(hi));
        g_Bh[((size_t)b * NPAD + row0 + r) * KH + k] = o;
    }
}

// ====== Kernel 2: fp16 GEMM, 1 mtile x 2 ntiles, A reused, B pipelined ======
__global__ void __launch_bounds__(128, 2)
mma_kernel(float* __restrict__ out) {
    extern __shared__ char sm[];
    __shared__ int4  s_nb[128];        // absolute neighbor cols for my 128 rows
    __shared__ float s_vs[2][128];
    __shared__ float s_red[2][128];
    __shared__ int   s_last;
    __shared__ float rL[4], rM[4];

    int tid = threadIdx.x;
    int wid = tid >> 5, l = tid & 31;
    int wm = wid & 1, wn = wid >> 1;        // 2 x 2 warp grid
    int ntg = blockIdx.x, mtile = blockIdx.y, b = blockIdx.z;

    uint32_t au = smem_u32(sm);
    const __half* Asrc = g_Ah + ((size_t)b * NPAD + mtile * 128) * KH;

    // group 0: A tile (reused for both ntiles)
#pragma unroll
    for (int tq = 0; tq < 16; ++tq) {
        int i = tq * 128 + tid, rr = i >> 4, g = i & 15;
        cp16(au + rr * ROWB + g * 16, Asrc + (size_t)rr * KH + g * 8);
    }
    CP_COMMIT();
    // groups 1,2: B tiles for ntile = ntg*2 + n
#pragma unroll
    for (int n = 0; n < 2; ++n) {
        const __half* Bsrc = g_Bh + ((size_t)b * NPAD + (ntg * 2 + n) * 128) * KH;
        uint32_t bb = au + (1 + n) * CHUNK;
#pragma unroll
        for (int tq = 0; tq < 16; ++tq) {
            int i = tq * 128 + tid, rr = i >> 4, g = i & 15;
            cp16(bb + rr * ROWB + g * 16, Bsrc + (size_t)rr * KH + g * 8);
        }
        CP_COMMIT();
    }

    // stage neighbor indices + vis while loads fly
    {
        int grow = mtile * 128 + tid;
        int gr = grow < NN ? grow : NN - 1;
        s_nb[tid] = *reinterpret_cast<const int4*>(&g_neigh[((size_t)b * NN + gr) * 4]);
#pragma unroll
        for (int n = 0; n < 2; ++n) {
            int gcol = (ntg * 2 + n) * 128 + tid;
            s_vs[n][tid] = (gcol < NN) ? g_visNeg[b * NN + gcol] : NEGBIG;
        }
    }

    // ldmatrix per-lane row offsets (warp tile 64x64)
    int lane7 = l & 7, mat = l >> 3, kh = mat >> 1;
    uint32_t arow[4], brow[4];
#pragma unroll
    for (int mf = 0; mf < 4; ++mf)
        arow[mf] = (uint32_t)(wm * 64 + mf * 16 + (mat & 1) * 8 + lane7) * ROWB;
#pragma unroll
    for (int bf = 0; bf < 4; ++bf)
        brow[bf] = (uint32_t)(wn * 64 + bf * 16 + (mat & 1) * 8 + lane7) * ROWB;

    float mrow[4][2];   // per (mf, half) running max across both ntiles? no: per tile
    // process the two ntiles sequentially
#pragma unroll
    for (int n = 0; n < 2; ++n) {
        if (n == 0) CP_WAIT(1);   // A + B0 landed (B1 still streaming)
        else        CP_WAIT(0);   // B1 landed
        __syncthreads();

        float cfr[4][8][4];
#pragma unroll
        for (int mf = 0; mf < 4; ++mf)
#pragma unroll
            for (int nf = 0; nf < 8; ++nf)
#pragma unroll
                for (int q = 0; q < 4; ++q) cfr[mf][nf][q] = 0.f;

        uint32_t bbase = au + (1 + n) * CHUNK;
#pragma unroll
        for (int ks = 0; ks < 8; ++ks) {
            uint32_t g16 = (uint32_t)((ks * 2 + kh) << 4);
            uint32_t af[4][4], bq[4][4];
#pragma unroll
            for (int mf = 0; mf < 4; ++mf) ldsm4(af[mf], au + arow[mf] + g16);
#pragma unroll
            for (int bf = 0; bf < 4; ++bf) ldsm4(bq[bf], bbase + brow[bf] + g16);
#pragma unroll
            for (int mf = 0; mf < 4; ++mf)
#pragma unroll
                for (int nf = 0; nf < 8; ++nf)
                    mma16816(cfr[mf][nf], af[mf],
                             bq[nf >> 1][nf & 1], bq[nf >> 1][2 + (nf & 1)]);
        }

        // epilogue for this ntile: vis add + neighbor-masked max per row
        int colbase = (ntg * 2 + n) * 128;
#pragma unroll
        for (int mf = 0; mf < 4; ++mf) {
#pragma unroll
            for (int half = 0; half < 2; ++half) {
                int rl = wm * 64 + mf * 16 + (l >> 2) + half * 8;
                int4 nb = s_nb[rl];
                float mx = NEGBIG;
#pragma unroll
                for (int nf = 0; nf < 8; ++nf) {
                    int lc0 = wn * 64 + nf * 8 + (l & 3) * 2;
                    int gc0 = colbase + lc0, gc1 = gc0 + 1;
                    float v0 = cfr[mf][nf][half * 2 + 0] + s_vs[n][lc0];
                    float v1 = cfr[mf][nf][half * 2 + 1] + s_vs[n][lc0 + 1];
                    bool m0 = (nb.x == gc0) | (nb.y == gc0) | (nb.z == gc0) | (nb.w == gc0);
                    bool m1 = (nb.x == gc1) | (nb.y == gc1) | (nb.z == gc1) | (nb.w == gc1);
                    mx = fmaxf(mx, m0 ? NEGBIG : v0);
                    mx = fmaxf(mx, m1 ? NEGBIG : v1);
                }
                mx = fmaxf(mx, __shfl_xor_sync(0xffffffffu, mx, 1));
                mx = fmaxf(mx, __shfl_xor_sync(0xffffffffu, mx, 2));
                if ((l & 3) == 0) s_red[wn][rl] = mx;
            }
        }
        __syncthreads();
        {
            float m = fmaxf(s_red[0][tid], s_red[1][tid]);
            int grow = mtile * 128 + tid;
            if (grow < NN) {
                float neg = sqrtf(fmaxf(2.f - 2.f * m, EPSF));
                atomicMin(&g_negMinI[b * NN + grow], __float_as_int(neg));
            }
        }
        __syncthreads();
    }
    (void)mrow;

    // last block: deterministic final reduction
    if (tid == 0) {
        __threadfence();
        s_last = (atomicAdd(&g_ctr, 1u) == TOTALB - 1) ? 1 : 0;
    }
    __syncthreads();
    if (s_last) {
        __threadfence();
        float aL = 0.f, aM = 0.f;
        for (int i = tid; i < BQ * NN; i += 128) {
            float neg = __int_as_float(g_negMinI[i]);
            float lv = fmaxf(g_posSim[i] - neg + 1.0f, 0.f);
            float mm = g_match[i];
            aL += lv * lv * mm;
            aM += mm;
        }
#pragma unroll
        for (int off = 16; off; off >>= 1) {
            aL += __shfl_xor_sync(0xffffffffu, aL, off);
            aM += __shfl_xor_sync(0xffffffffu, aM, off);
        }
        if (l == 0) { rL[wid] = aL; rM[wid] = aM; }
        __syncthreads();
        if (tid == 0) {
            float sL = 0.f, sM = 0.f;
#pragma unroll
            for (int q = 0; q < 4; ++q) { sL += rL[q]; sM += rM[q]; }
            out[0] = sL / sM;
        }
    }
}

// ---------------- launch ----------------
extern "C" void kernel_launch(void* const* d_in, const int* in_sizes, int n_in,
                              void* d_out, int out_size) {
    // metadata order: score1, score2, desc1, desc2, homo12, homo21
    const float* desc1  = (const float*)d_in[2];
    const float* desc2  = (const float*)d_in[3];
    const float* homo12 = (const float*)d_in[4];
    const float* homo21 = (const float*)d_in[5];

    cudaFuncSetAttribute(mma_kernel, cudaFuncAttributeMaxDynamicSharedMemorySize,
                         SMEM_BYTES);
    prep_kernel<<<(BQ * NN * 8 + 255) / 256, 256>>>(desc1, desc2, homo12, homo21);
    split_kernel<<<dim3(MT, BQ), 256>>>(desc1, desc2);
    dim3 g(NTG, MT, BQ);
    mma_kernel<<<g, 128, SMEM_BYTES>>>((float*)d_out);
}

// round 16
// speedup vs baseline: 1.1337x; 1.0003x over previous
#include <cuda_runtime.h>
#include <cuda_fp16.h>
#include <math.h>
#include <stdint.h>

// Problem constants (b=2, c=64, H=480, W=640, gs=8 -> hc=60, wc=80, n=4800)
#define BQ 2
#define CC 64
#define HC 60
#define WCC 80
#define NN 4800
#define HH 480
#define WW 640
#define EPSF 1e-8f
#define NEGBIG -1e30f

// GEMM: M=N=4800 (pad 4864), K=128 fp16 (hi|lo split), 128x128 tiles
// Each block: 1 mtile x 2 ntiles (A reused, B double-streamed)
#define KH 128
#define NPAD 4864
#define MT 38
#define NTG 19                         // ntile pairs
#define TOTALB (NTG * MT * BQ)         // 1444
#define ROWB 272                       // 17 x 16B, odd -> conflict-free
#define CHUNK (128 * ROWB)             // 34816 bytes per matrix tile
#define SMEM_BYTES (3 * CHUNK)         // A + B0 + B1 = 104448

// fused prep+split dispatcher: blocks [0, PREPB) prep, [PREPB, PREPB+SPLITB) split
#define PREPB ((BQ * NN * 8 + 255) / 256)   // 300
#define SPLITB (MT * BQ)                    // 76

// ---------------- scratch (no allocations allowed) ----------------
__device__ float    g_visNeg[BQ * NN];     // 0 if visible else -1e30
__device__ float    g_posSim[BQ * NN];
__device__ float    g_match[BQ * NN];
__device__ int      g_neigh[BQ * NN * 4];
__device__ int      g_negMinI[BQ * NN];
__device__ unsigned g_ctr;
__device__ __align__(16) __half g_Ah[(size_t)BQ * NPAD * KH];
__device__ __align__(16) __half g_Bh[(size_t)BQ * NPAD * KH];

__device__ __forceinline__ uint32_t smem_u32(const void* p) {
    uint32_t a;
    asm("{ .reg .u64 t; cvta.to.shared.u64 t, %1; cvt.u32.u64 %0, t; }"
        : "=r"(a) : "l"(p));
    return a;
}
__device__ __forceinline__ void ldsm4(uint32_t* r, uint32_t addr) {
    asm volatile("ldmatrix.sync.aligned.m8n8.x4.shared.b16 {%0,%1,%2,%3}, [%4];"
                 : "=r"(r[0]), "=r"(r[1]), "=r"(r[2]), "=r"(r[3]) : "r"(addr));
}
__device__ __forceinline__ void mma16816(float* c, const uint32_t* a,
                                         uint32_t b0, uint32_t b1) {
    asm volatile(
        "mma.sync.aligned.m16n8k16.row.col.f32.f16.f16.f32 "
        "{%0,%1,%2,%3}, {%4,%5,%6,%7}, {%8,%9}, {%0,%1,%2,%3};"
        : "+f"(c[0]), "+f"(c[1]), "+f"(c[2]), "+f"(c[3])
        : "r"(a[0]), "r"(a[1]), "r"(a[2]), "r"(a[3]), "r"(b0), "r"(b1));
}
__device__ __forceinline__ void cp16(uint32_t dst, const void* src) {
    asm volatile("cp.async.cg.shared.global [%0], [%1], 16;"
                 :: "r"(dst), "l"(src) : "memory");
}
#define CP_COMMIT() asm volatile("cp.async.commit_group;" ::: "memory")
#define CP_WAIT(n)  asm volatile("cp.async.wait_group %0;" :: "n"(n) : "memory")

__device__ __forceinline__ float inb_grid(float yi, float xi) {
    return (yi >= 0.f && yi <= (float)(HC - 1) && xi >= 0.f && xi <= (float)(WCC - 1)) ? 1.f : 0.f;
}

// ---- prep body: 8 THREADS per row (parallel + coalesced) ----
__device__ void prep_body(int bx, int tidx,
                          const float* __restrict__ desc1,
                          const float* __restrict__ desc2,
                          const float* __restrict__ homo12,
                          const float* __restrict__ homo21) {
    int t8 = bx * 256 + tidx;
    if (t8 == 0) g_ctr = 0u;
    int t = t8 >> 3;          // global row id (b*NN + r)
    int p = t8 & 7;           // part 0..7
    if (t >= BQ * NN) return;
    int b = t / NN, r = t % NN;
    int iy = r / WCC, ix = r % WCC;

    // ---- visibility: one dy-row of 8 pixels per part, division-free ----
    {
        const float* h = homo21 + b * 9;
        float h0 = h[0], h1 = h[1], h2 = h[2], h3 = h[3], h4 = h[4],
              h5 = h[5], h6 = h[6], h7 = h[7], h8 = h[8];
        float cx0 = (float)(ix * 8);
        float y = (float)(iy * 8 + p);
        float qxr = h0 * cx0 + h1 * y + h2;
        float qyr = h3 * cx0 + h4 * y + h5;
        float qzr = h6 * cx0 + h7 * y + h8;
        bool ok = true;
#pragma unroll
        for (int dx = 0; dx < 8; ++dx) {
            float qx = qxr + h0 * (float)dx;
            float qy = qyr + h3 * (float)dx;
            float z  = qzr + h6 * (float)dx + EPSF;
            ok = ok && ((qy + z) * z > 0.f)
                    && (((float)HH * z - qy) * z > 0.f)
                    && ((qx + z) * z > 0.f)
                    && (((float)WW * z - qx) * z > 0.f);
        }
        unsigned oku = ok ? 1u : 0u;
        oku &= __shfl_xor_sync(0xffffffffu, oku, 1);
        oku &= __shfl_xor_sync(0xffffffffu, oku, 2);
        oku &= __shfl_xor_sync(0xffffffffu, oku, 4);
        if (p == 0) {
            g_visNeg[t] = oku ? 0.f : NEGBIG;
            g_negMinI[t] = 0x7F800000;
        }
    }

    // ---- warp point under homo12 (all parts, cheap) ----
    const float* h = homo12 + b * 9;
    float px = (float)(ix * 8) + 3.5f;
    float py = (float)(iy * 8) + 3.5f;
    float qx = h[0] * px + h[1] * py + h[2];
    float qy = h[3] * px + h[4] * py + h[5];
    float qz = h[6] * px + h[7] * py + h[8];
    float wx = qx / (qz + EPSF);
    float wy = qy / (qz + EPSF);
    float dyc = (wy - 3.5f) * 0.125f;
    float dxc = (wx - 3.5f) * 0.125f;

    // ---- 4-NN in clamped 4x4 window (part 0 only; tie -> lower index) ----
    if (p == 0) {
        float a2 = wy * wy + wx * wx;
        int xlo = (int)fminf(fmaxf(floorf(dxc) - 1.f, 0.f), (float)(WCC - 4));
        int ylo = (int)fminf(fmaxf(floorf(dyc) - 1.f, 0.f), (float)(HC - 4));
        float bd[4] = {1e30f, 1e30f, 1e30f, 1e30f};
        int bi[4] = {-1, -1, -1, -1};
#pragma unroll
        for (int jy = 0; jy < 4; ++jy) {
            int iyc = ylo + jy;
            float cy = (float)(iyc * 8) + 3.5f;
#pragma unroll
            for (int jx = 0; jx < 4; ++jx) {
                int ixc = xlo + jx;
                float cx = (float)(ixc * 8) + 3.5f;
                float d = a2 + cy * cy + cx * cx - 2.f * (wy * cy + wx * cx);
                int m = iyc * WCC + ixc;
                if (d < bd[3]) {
                    int k = 3;
                    while (k > 0 && d < bd[k - 1]) {
                        bd[k] = bd[k - 1]; bi[k] = bi[k - 1]; --k;
                    }
                    bd[k] = d; bi[k] = m;
                }
            }
        }
        int* o = &g_neigh[(size_t)t * 4];
        o[0] = bi[0]; o[1] = bi[1]; o[2] = bi[2]; o[3] = bi[3];
    }

    // ---- bilinear w_desc1 + pos_sim: 8 channels per part ----
    float y0 = floorf(dyc), x0 = floorf(dxc);
    float fy = dyc - y0, fx = dxc - x0;
    float e00 = (1.f - fy) * (1.f - fx) * inb_grid(y0, x0);
    float e01 = (1.f - fy) * fx         * inb_grid(y0, x0 + 1.f);
    float e10 = fy * (1.f - fx)         * inb_grid(y0 + 1.f, x0);
    float e11 = fy * fx                 * inb_grid(y0 + 1.f, x0 + 1.f);
    int yc0 = (int)fminf(fmaxf(y0, 0.f), (float)(HC - 1));
    int yc1 = (int)fminf(fmaxf(y0 + 1.f, 0.f), (float)(HC - 1));
    int xc0 = (int)fminf(fmaxf(x0, 0.f), (float)(WCC - 1));
    int xc1 = (int)fminf(fmaxf(x0 + 1.f, 0.f), (float)(WCC - 1));
    int c00 = yc0 * WCC + xc0, c01 = yc0 * WCC + xc1;
    int c10 = yc1 * WCC + xc0, c11 = yc1 * WCC + xc1;

    const float* d2b = desc2 + ((size_t)b * CC + p * 8) * NN;
    const float* d1b = desc1 + ((size_t)b * CC + p * 8) * NN + r;
    float sq = 0.f, dp = 0.f;
#pragma unroll
    for (int i = 0; i < 8; ++i) {
        const float* pp = d2b + (size_t)i * NN;
        float v = e00 * pp[c00] + e01 * pp[c01] + e10 * pp[c10] + e11 * pp[c11];
        sq += v * v;
        dp += d1b[(size_t)i * NN] * v;
    }
    sq += __shfl_xor_sync(0xffffffffu, sq, 1);
    dp += __shfl_xor_sync(0xffffffffu, dp, 1);
    sq += __shfl_xor_sync(0xffffffffu, sq, 2);
    dp += __shfl_xor_sync(0xffffffffu, dp, 2);
    sq += __shfl_xor_sync(0xffffffffu, sq, 4);
    dp += __shfl_xor_sync(0xffffffffu, dp, 4);

    if (p == 0) {
        float posdot = dp / (sqrtf(sq) + EPSF);
        g_posSim[t] = sqrtf(fmaxf(2.f - 2.f * posdot, EPSF));
        g_match[t] =
            (wy >= 0.f && wy <= (float)(HH - 1) && wx >= 0.f && wx <= (float)(WW - 1)) ? 1.f : 0.f;
    }
}

// ---- split body: f32 -> fp16 hi|lo scratch (K = 64 hi + 64 lo) ----
__device__ void split_body(float (*sd)[129], int b, int row0, int tid,
                           const float* __restrict__ desc1,
                           const float* __restrict__ desc2) {
    for (int i = tid; i < CC * 128; i += 256) {
        int ch = i >> 7, r = i & 127;
        int gr = row0 + r;
        sd[ch][r] = (gr < NN) ? desc1[(size_t)(b * CC + ch) * NN + gr] : 0.f;
    }
    __syncthreads();
    for (int i = tid; i < 128 * KH; i += 256) {
        int r = i >> 7, k = i & 127;
        float v = sd[k & 63][r];
        __half hi = __float2half_rn(v);
        __half o = (k < 64) ? hi : __float2half_rn(v - __half2float(hi));
        g_Ah[((size_t)b * NPAD + row0 + r) * KH + k] = o;
    }
    __syncthreads();

    for (int i = tid; i < CC * 128; i += 256) {
        int ch = i >> 7, r = i & 127;
        int gr = row0 + r;
        sd[ch][r] = (gr < NN) ? desc2[(size_t)(b * CC + ch) * NN + gr] : 0.f;
    }
    __syncthreads();
    for (int i = tid; i < 128 * KH; i += 256) {
        int r = i >> 7, k = i & 127;
        float v = sd[k & 63][r];
        __half hi = __float2half_rn(v);
        __half o = (k < 64) ? hi : __float2half_rn(v - __half2float(hi));
        g_Bh[((size_t)b * NPAD + row0 + r) * KH + k] = o;
    }
}

// ====== Kernel 0: fused prep + split (independent work, overlapped) ======
__global__ void __launch_bounds__(256)
prepsplit_kernel(const float* __restrict__ desc1,
                 const float* __restrict__ desc2,
                 const float* __restrict__ homo12,
                 const float* __restrict__ homo21) {
    __shared__ float sd[CC][129];
    int bx = blockIdx.x;
    if (bx < PREPB) {
        prep_body(bx, threadIdx.x, desc1, desc2, homo12, homo21);
    } else {
        int sb = bx - PREPB;              // 0..75
        int b = sb / MT;
        int row0 = (sb % MT) * 128;
        split_body(sd, b, row0, threadIdx.x, desc1, desc2);
    }
}

// ====== Kernel 1: fp16 GEMM, 1 mtile x 2 ntiles, A reused, B pipelined ======
__global__ void __launch_bounds__(128, 2)
mma_kernel(float* __restrict__ out) {
    extern __shared__ char sm[];
    __shared__ int4  s_nb[128];        // absolute neighbor cols for my 128 rows
    __shared__ float s_vs[2][128];
    __shared__ float s_red[2][128];
    __shared__ int   s_last;
    __shared__ float rL[4], rM[4];

    int tid = threadIdx.x;
    int wid = tid >> 5, l = tid & 31;
    int wm = wid & 1, wn = wid >> 1;        // 2 x 2 warp grid
    int ntg = blockIdx.x, mtile = blockIdx.y, b = blockIdx.z;

    uint32_t au = smem_u32(sm);
    const __half* Asrc = g_Ah + ((size_t)b * NPAD + mtile * 128) * KH;

    // group 0: A tile (reused for both ntiles)
#pragma unroll
    for (int tq = 0; tq < 16; ++tq) {
        int i = tq * 128 + tid, rr = i >> 4, g = i & 15;
        cp16(au + rr * ROWB + g * 16, Asrc + (size_t)rr * KH + g * 8);
    }
    CP_COMMIT();
    // groups 1,2: B tiles for ntile = ntg*2 + n
#pragma unroll
    for (int n = 0; n < 2; ++n) {
        const __half* Bsrc = g_Bh + ((size_t)b * NPAD + (ntg * 2 + n) * 128) * KH;
        uint32_t bb = au + (1 + n) * CHUNK;
#pragma unroll
        for (int tq = 0; tq < 16; ++tq) {
            int i = tq * 128 + tid, rr = i >> 4, g = i & 15;
            cp16(bb + rr * ROWB + g * 16, Bsrc + (size_t)rr * KH + g * 8);
        }
        CP_COMMIT();
    }

    // stage neighbor indices + vis while loads fly
    {
        int grow = mtile * 128 + tid;
        int gr = grow < NN ? grow : NN - 1;
        s_nb[tid] = *reinterpret_cast<const int4*>(&g_neigh[((size_t)b * NN + gr) * 4]);
#pragma unroll
        for (int n = 0; n < 2; ++n) {
            int gcol = (ntg * 2 + n) * 128 + tid;
            s_vs[n][tid] = (gcol < NN) ? g_visNeg[b * NN + gcol] : NEGBIG;
        }
    }

    // ldmatrix per-lane row offsets (warp tile 64x64)
    int lane7 = l & 7, mat = l >> 3, kh = mat >> 1;
    uint32_t arow[4], brow[4];
#pragma unroll
    for (int mf = 0; mf < 4; ++mf)
        arow[mf] = (uint32_t)(wm * 64 + mf * 16 + (mat & 1) * 8 + lane7) * ROWB;
#pragma unroll
    for (int bf = 0; bf < 4; ++bf)
        brow[bf] = (uint32_t)(wn * 64 + bf * 16 + (mat & 1) * 8 + lane7) * ROWB;

    // process the two ntiles sequentially
#pragma unroll
    for (int n = 0; n < 2; ++n) {
        if (n == 0) CP_WAIT(1);   // A + B0 landed (B1 still streaming)
        else        CP_WAIT(0);   // B1 landed
        __syncthreads();

        float cfr[4][8][4];
#pragma unroll
        for (int mf = 0; mf < 4; ++mf)
#pragma unroll
            for (int nf = 0; nf < 8; ++nf)
#pragma unroll
                for (int q = 0; q < 4; ++q) cfr[mf][nf][q] = 0.f;

        uint32_t bbase = au + (1 + n) * CHUNK;
#pragma unroll
        for (int ks = 0; ks < 8; ++ks) {
            uint32_t g16 = (uint32_t)((ks * 2 + kh) << 4);
            uint32_t af[4][4], bq[4][4];
#pragma unroll
            for (int mf = 0; mf < 4; ++mf) ldsm4(af[mf], au + arow[mf] + g16);
#pragma unroll
            for (int bf = 0; bf < 4; ++bf) ldsm4(bq[bf], bbase + brow[bf] + g16);
#pragma unroll
            for (int mf = 0; mf < 4; ++mf)
#pragma unroll
                for (int nf = 0; nf < 8; ++nf)
                    mma16816(cfr[mf][nf], af[mf],
                             bq[nf >> 1][nf & 1], bq[nf >> 1][2 + (nf & 1)]);
        }

        // epilogue for this ntile: vis add + neighbor-masked max per row
        int colbase = (ntg * 2 + n) * 128;
#pragma unroll
        for (int mf = 0; mf < 4; ++mf) {
#pragma unroll
            for (int half = 0; half < 2; ++half) {
                int rl = wm * 64 + mf * 16 + (l >> 2) + half * 8;
                int4 nb = s_nb[rl];
                float mx = NEGBIG;
#pragma unroll
                for (int nf = 0; nf < 8; ++nf) {
                    int lc0 = wn * 64 + nf * 8 + (l & 3) * 2;
                    int gc0 = colbase + lc0, gc1 = gc0 + 1;
                    float v0 = cfr[mf][nf][half * 2 + 0] + s_vs[n][lc0];
                    float v1 = cfr[mf][nf][half * 2 + 1] + s_vs[n][lc0 + 1];
                    bool m0 = (nb.x == gc0) | (nb.y == gc0) | (nb.z == gc0) | (nb.w == gc0);
                    bool m1 = (nb.x == gc1) | (nb.y == gc1) | (nb.z == gc1) | (nb.w == gc1);
                    mx = fmaxf(mx, m0 ? NEGBIG : v0);
                    mx = fmaxf(mx, m1 ? NEGBIG : v1);
                }
                mx = fmaxf(mx, __shfl_xor_sync(0xffffffffu, mx, 1));
                mx = fmaxf(mx, __shfl_xor_sync(0xffffffffu, mx, 2));
                if ((l & 3) == 0) s_red[wn][rl] = mx;
            }
        }
        __syncthreads();
        {
            float m = fmaxf(s_red[0][tid], s_red[1][tid]);
            int grow = mtile * 128 + tid;
            if (grow < NN) {
                float neg = sqrtf(fmaxf(2.f - 2.f * m, EPSF));
                atomicMin(&g_negMinI[b * NN + grow], __float_as_int(neg));
            }
        }
        __syncthreads();
    }

    // last block: deterministic final reduction
    if (tid == 0) {
        __threadfence();
        s_last = (atomicAdd(&g_ctr, 1u) == TOTALB - 1) ? 1 : 0;
    }
    __syncthreads();
    if (s_last) {
        __threadfence();
        float aL = 0.f, aM = 0.f;
        for (int i = tid; i < BQ * NN; i += 128) {
            float neg = __int_as_float(g_negMinI[i]);
            float lv = fmaxf(g_posSim[i] - neg + 1.0f, 0.f);
            float mm = g_match[i];
            aL += lv * lv * mm;
            aM += mm;
        }
#pragma unroll
        for (int off = 16; off; off >>= 1) {
            aL += __shfl_xor_sync(0xffffffffu, aL, off);
            aM += __shfl_xor_sync(0xffffffffu, aM, off);
        }
        if (l == 0) { rL[wid] = aL; rM[wid] = aM; }
        __syncthreads();
        if (tid == 0) {
            float sL = 0.f, sM = 0.f;
#pragma unroll
            for (int q = 0; q < 4; ++q) { sL += rL[q]; sM += rM[q]; }
            out[0] = sL / sM;
        }
    }
}

// ---------------- launch ----------------
extern "C" void kernel_launch(void* const* d_in, const int* in_sizes, int n_in,
                              void* d_out, int out_size) {
    // metadata order: score1, score2, desc1, desc2, homo12, homo21
    const float* desc1  = (const float*)d_in[2];
    const float* desc2  = (const float*)d_in[3];
    const float* homo12 = (const float*)d_in[4];
    const float* homo21 = (const float*)d_in[5];

    cudaFuncSetAttribute(mma_kernel, cudaFuncAttributeMaxDynamicSharedMemorySize,
                         SMEM_BYTES);
    prepsplit_kernel<<<PREPB + SPLITB, 256>>>(desc1, desc2, homo12, homo21);
    dim3 g(NTG, MT, BQ);
    mma_kernel<<<g, 128, SMEM_BYTES>>>((float*)d_out);
}